// round 12
// baseline (speedup 1.0000x reference)
#include <cuda_runtime.h>
#include <cuda_bf16.h>
#include <cstdint>

#define BB   8
#define SRC  512
#define TGT  128
#define ED   512
#define DD   512
#define TT   4

// Scratch (device globals: allocation-free per harness rules)
// NOTE: g_mp/g_dp hold Eb = exp(2*mp), Ea = exp(2*dp) (written by gemm_tc).
__device__ float g_mp[BB * SRC * DD];          // 8 MB
__device__ float g_dp[BB * TGT * DD];          // 2 MB
__device__ float g_a [BB * TGT * SRC];         // 2 MB: UNNORMALIZED exp(logit)
__device__ float g_psum[BB * TGT * 4];         // per-(b,t,s-quarter) partial sums
__device__ __nv_bfloat16 g_Ah[5120 * 512];     // A hi (memory rows 0..4095, dec 4096..5119)
__device__ __nv_bfloat16 g_Al[5120 * 512];     // A lo
__device__ __nv_bfloat16 g_Wth[2 * 512 * 512]; // W^T hi: sel 0 = Wa_d, 1 = Wa_m; [n][k]
__device__ __nv_bfloat16 g_Wtl[2 * 512 * 512]; // W^T lo

__device__ __forceinline__ float fast_rcp(float x) {
    float y;
    asm("rcp.approx.ftz.f32 %0, %1;" : "=f"(y) : "f"(x));   // bare MUFU.RCP
    return y;
}

__device__ __forceinline__ void cp_async16(void* smem_dst, const void* gmem_src) {
    uint32_t d = (uint32_t)__cvta_generic_to_shared(smem_dst);
    asm volatile("cp.async.ca.shared.global [%0], [%1], 16;\n" :: "r"(d), "l"(gmem_src));
}
#define CP_COMMIT() asm volatile("cp.async.commit_group;\n")
#define CP_WAIT1()  asm volatile("cp.async.wait_group 1;\n")
#define CP_WAIT0()  asm volatile("cp.async.wait_group 0;\n")

__device__ __forceinline__ void ldm_x4(uint32_t* r, uint32_t addr) {
    asm volatile("ldmatrix.sync.aligned.m8n8.x4.shared.b16 {%0,%1,%2,%3}, [%4];"
                 : "=r"(r[0]), "=r"(r[1]), "=r"(r[2]), "=r"(r[3]) : "r"(addr));
}
__device__ __forceinline__ void mma16816(float* c, const uint32_t* a, const uint32_t* b) {
    asm volatile("mma.sync.aligned.m16n8k16.row.col.f32.bf16.bf16.f32 "
                 "{%0,%1,%2,%3}, {%4,%5,%6,%7}, {%8,%9}, {%0,%1,%2,%3};"
                 : "+f"(c[0]), "+f"(c[1]), "+f"(c[2]), "+f"(c[3])
                 : "r"(a[0]), "r"(a[1]), "r"(a[2]), "r"(a[3]), "r"(b[0]), "r"(b[1]));
}

// ---------------------------------------------------------------------------
// Conversion: fp32 -> bf16 (hi, lo) for A = [memory ; dec]  (5120 x 512)
// ---------------------------------------------------------------------------
__global__ void __launch_bounds__(256) conv_a(
    const float* __restrict__ memory, const float* __restrict__ dec)
{
    const int idx = blockIdx.x * 256 + threadIdx.x;          // float4 index
    const float4 v = (idx < 524288) ? ((const float4*)memory)[idx]
                                    : ((const float4*)dec)[idx - 524288];
    float xs[4] = {v.x, v.y, v.z, v.w};
    __nv_bfloat16 h[4], l[4];
    #pragma unroll
    for (int i = 0; i < 4; i++) {
        h[i] = __float2bfloat16(xs[i]);
        l[i] = __float2bfloat16(xs[i] - __bfloat162float(h[i]));
    }
    ((__nv_bfloat162*)g_Ah)[idx * 2]     = __halves2bfloat162(h[0], h[1]);
    ((__nv_bfloat162*)g_Ah)[idx * 2 + 1] = __halves2bfloat162(h[2], h[3]);
    ((__nv_bfloat162*)g_Al)[idx * 2]     = __halves2bfloat162(l[0], l[1]);
    ((__nv_bfloat162*)g_Al)[idx * 2 + 1] = __halves2bfloat162(l[2], l[3]);
}

// ---------------------------------------------------------------------------
// Conversion: W^T hi/lo.  Wt[sel][n][k] = Wa[sel*512 + k][n];  sel 0=Wa_d, 1=Wa_m
// ---------------------------------------------------------------------------
__global__ void __launch_bounds__(256) conv_w(const float* __restrict__ Wa)
{
    __shared__ float s[32][33];
    const int tx = threadIdx.x, ty = threadIdx.y;            // 32 x 8
    const int bx = blockIdx.x, by = blockIdx.y, sel = blockIdx.z;

    #pragma unroll
    for (int j = 0; j < 32; j += 8)
        s[ty + j][tx] = Wa[(size_t)(sel * 512 + by * 32 + ty + j) * 512 + bx * 32 + tx];
    __syncthreads();

    #pragma unroll
    for (int j = 0; j < 32; j += 8) {
        const int n = bx * 32 + ty + j;
        const int k = by * 32 + tx;
        float x = s[tx][ty + j];
        __nv_bfloat16 h = __float2bfloat16(x);
        __nv_bfloat16 l = __float2bfloat16(x - __bfloat162float(h));
        const size_t o = (size_t)(sel * 512 + n) * 512 + k;
        g_Wth[o] = h;
        g_Wtl[o] = l;
    }
}

// ---------------------------------------------------------------------------
// Tensor-core projection GEMM via mma.sync (bf16 3-way split, fp32 accum).
// C tile 128x128, grid (4, 40) = 160 CTAs -> fits in ONE wave (<=296 resident
// at 2 blocks/SM), no tail. Warp tile 32x64 (2 m16 x 8 n8): per k16-chunk
// 48 mma : 12 ldmatrix. K-chunks of 16, cp.async double-buffered (48KB smem).
// EPILOGUE stores exp(2*proj) for the score kernel's rcp formulation.
// ---------------------------------------------------------------------------
#define PITCH 48
#define OA_H  0
#define OA_L  6144
#define OW_H  12288
#define OW_L  18432
#define BUFSZ 24576

__global__ void __launch_bounds__(256, 2) gemm_tc()
{
    __shared__ char sm[2 * BUFSZ];                // 48 KB
    const uint32_t sb = (uint32_t)__cvta_generic_to_shared(sm);

    const int tid  = threadIdx.x;
    const int lane = tid & 31;
    const int w    = tid >> 5;
    const int wm   = w >> 1;                      // 0..3 (m, 32 rows each)
    const int wn   = w & 1;                       // 0..1 (n, 64 cols each)
    const int bn   = blockIdx.x;                  // 0..3 (128-col tiles)
    const int by   = blockIdx.y;                  // 0..39

    const int m_base = by * 128;
    const int sel    = (by < 32) ? 1 : 0;
    float* C = (by < 32) ? (g_mp + (size_t)by * 128 * 512)
                         : (g_dp + (size_t)(by - 32) * 128 * 512);
    const __nv_bfloat16* Wh = g_Wth + (size_t)sel * 512 * 512 + (size_t)bn * 128 * 512;
    const __nv_bfloat16* Wl = g_Wtl + (size_t)sel * 512 * 512 + (size_t)bn * 128 * 512;

    // loader: 4 regions x 128 rows x 2 16B-segs; each thread: row=tid>>1, seg=tid&1
    const int lrow = tid >> 1;
    const int lseg = tid & 1;

    auto issue = [&](int kc, int buf) {
        char* B = sm + buf * BUFSZ;
        const size_t koff = (size_t)kc * 16 + lseg * 8;
        const uint32_t dso = lrow * PITCH + lseg * 16;
        cp_async16(B + OA_H + dso, g_Ah + (size_t)(m_base + lrow) * 512 + koff);
        cp_async16(B + OA_L + dso, g_Al + (size_t)(m_base + lrow) * 512 + koff);
        cp_async16(B + OW_H + dso, Wh + (size_t)lrow * 512 + koff);
        cp_async16(B + OW_L + dso, Wl + (size_t)lrow * 512 + koff);
        CP_COMMIT();
    };

    const uint32_t a_off = (uint32_t)((wm * 32 + (lane & 15)) * PITCH + (lane >> 4) * 16);
    const uint32_t b_off = (uint32_t)((wn * 64 + (lane & 7) + ((lane >> 4) * 8)) * PITCH
                                      + (((lane >> 3) & 1) * 16));

    float acc[2][8][4];
    #pragma unroll
    for (int i = 0; i < 2; i++)
        #pragma unroll
        for (int j = 0; j < 8; j++)
            #pragma unroll
            for (int e = 0; e < 4; e++) acc[i][j][e] = 0.f;

    issue(0, 0);

    for (int kc = 0; kc < 32; kc++) {
        if (kc < 31) { issue(kc + 1, (kc + 1) & 1); CP_WAIT1(); }
        else         { CP_WAIT0(); }
        __syncthreads();

        const uint32_t base = sb + (kc & 1) * BUFSZ;
        uint32_t ah[2][4], al[2][4];
        #pragma unroll
        for (int i = 0; i < 2; i++) {
            ldm_x4(ah[i], base + OA_H + a_off + i * 16 * PITCH);
            ldm_x4(al[i], base + OA_L + a_off + i * 16 * PITCH);
        }

        #pragma unroll
        for (int jj = 0; jj < 4; jj++) {           // 16 n-cols per jj
            uint32_t bh[4], bl[4];
            ldm_x4(bh, base + OW_H + b_off + jj * 16 * PITCH);
            ldm_x4(bl, base + OW_L + b_off + jj * 16 * PITCH);
            #pragma unroll
            for (int h = 0; h < 2; h++) {          // n8 within jj
                const int j = jj * 2 + h;
                const uint32_t* ph = &bh[2 * h];
                const uint32_t* pl = &bl[2 * h];
                #pragma unroll
                for (int i = 0; i < 2; i++) {
                    mma16816(acc[i][j], ah[i], ph);
                    mma16816(acc[i][j], ah[i], pl);
                    mma16816(acc[i][j], al[i], ph);
                }
            }
        }
        __syncthreads();
    }

    // epilogue: store E = exp(2 * proj)
    #pragma unroll
    for (int i = 0; i < 2; i++) {
        const int r0 = wm * 32 + i * 16 + (lane >> 2);
        #pragma unroll
        for (int j = 0; j < 8; j++) {
            const int c0 = bn * 128 + wn * 64 + j * 8 + (lane & 3) * 2;
            *(float2*)(C + (size_t)r0 * 512 + c0) =
                make_float2(__expf(2.f * acc[i][j][0]), __expf(2.f * acc[i][j][1]));
            *(float2*)(C + (size_t)(r0 + 8) * 512 + c0) =
                make_float2(__expf(2.f * acc[i][j][2]), __expf(2.f * acc[i][j][3]));
        }
    }
}

// ---------------------------------------------------------------------------
// Score -> unnormalized p = exp(e) in g_a + per-quarter partial sums g_psum.
// e[t,s] = -2 * sum_k Va_k / (1 + Ea[t,k]*Eb[s,k])  (+const, cancels in
// softmax; |e| bounded ~36 -> exp safe in fp32, no max pass).
// Grid (TGT/TT, 4 s-quarters, BB) = 1024 blocks; tile 128 x 32, cp.async
// double-buffered; 4 blocks/SM.
// ---------------------------------------------------------------------------
#define STW (128 * 36)

__global__ void __launch_bounds__(256, 4) score_kernel(
    const float* __restrict__ Va,
    const int* __restrict__ mask)
{
    __shared__ float s_mp[2 * STW];     // 36 KB
    __shared__ float s_dp[TT * 512];    //  8 KB
    __shared__ float s_va[512];         //  2 KB
    __shared__ float s_red[TT * 4];

    const int b    = blockIdx.z;
    const int q4   = blockIdx.y;        // s-quarter 0..3
    const int t0   = blockIdx.x * TT;
    const int tid  = threadIdx.x;
    const int lane = tid & 31;
    const int w    = tid >> 5;
    const int wr4  = w & 3;             // row-group
    const int tg   = (w >> 2) * 2;      // t-pair base

    {
        const float4* dpg = (const float4*)(g_dp + (size_t)(b * TGT + t0) * 512);
        ((float4*)s_dp)[tid]       = dpg[tid];
        ((float4*)s_dp)[tid + 256] = dpg[tid + 256];
        if (tid < 128) ((float4*)s_va)[tid] = ((const float4*)Va)[tid];
    }

    const float* mpg = g_mp + (size_t)(b * SRC + q4 * 128) * 512;

    // loader: 1024 float4 per chunk, 4 per thread
    const int lr[4] = { (tid + 0) >> 3, (tid + 256) >> 3, (tid + 512) >> 3, (tid + 768) >> 3 };
    const int lc4   = (tid & 7) << 2;

    auto issue = [&](int kc, int buf) {
        float* dst = s_mp + buf * STW;
        const float* src = mpg + kc * 32;
        #pragma unroll
        for (int i = 0; i < 4; i++)
            cp_async16(dst + lr[i] * 36 + lc4, src + (size_t)lr[i] * 512 + lc4);
        CP_COMMIT();
    };

    issue(0, 0);

    float acc[2] = {0.f, 0.f};
    const int myrow = wr4 * 32 + lane;

    for (int c = 0; c < 16; c++) {
        if (c < 15) { issue(c + 1, (c + 1) & 1); CP_WAIT1(); }
        else        { CP_WAIT0(); }
        __syncthreads();

        const float* mrow_s = s_mp + (c & 1) * STW + myrow * 36;
        const int kc = c * 32;
        #pragma unroll
        for (int k = 0; k < 32; k += 4) {
            float4 m4 = *(const float4*)(mrow_s + k);           // Eb
            float4 v4 = *(const float4*)(s_va + kc + k);
            #pragma unroll
            for (int tt = 0; tt < 2; tt++) {
                float4 d4 = *(const float4*)(s_dp + (tg + tt) * 512 + kc + k);  // Ea
                float r0v = fast_rcp(fmaf(d4.x, m4.x, 1.f));
                float r1v = fast_rcp(fmaf(d4.y, m4.y, 1.f));
                float r2v = fast_rcp(fmaf(d4.z, m4.z, 1.f));
                float r3v = fast_rcp(fmaf(d4.w, m4.w, 1.f));
                acc[tt] = fmaf(v4.x, r0v, acc[tt]);
                acc[tt] = fmaf(v4.y, r1v, acc[tt]);
                acc[tt] = fmaf(v4.z, r2v, acc[tt]);
                acc[tt] = fmaf(v4.w, r3v, acc[tt]);
            }
        }
        __syncthreads();   // compute done before buffer refilled
    }

    // p = exp(-2*acc), masked to 0
    const int sg = q4 * 128 + myrow;
    const bool mok = (mask[b * SRC + sg] != 0);
    float p[2];
    #pragma unroll
    for (int tt = 0; tt < 2; tt++)
        p[tt] = mok ? __expf(-2.f * acc[tt]) : 0.f;

    // per-t partial sums over this block's 128 s (4 warps share each t)
    #pragma unroll
    for (int tt = 0; tt < 2; tt++) {
        float s = p[tt];
        #pragma unroll
        for (int o = 16; o; o >>= 1) s += __shfl_xor_sync(0xffffffffu, s, o);
        if (lane == 0) s_red[(tg + tt) * 4 + wr4] = s;
    }
    __syncthreads();
    if (tid < TT) {
        const float* r = s_red + tid * 4;
        g_psum[(b * TGT + t0 + tid) * 4 + q4] = r[0] + r[1] + r[2] + r[3];
    }

    #pragma unroll
    for (int tt = 0; tt < 2; tt++)
        g_a[(size_t)(b * TGT + t0 + tg + tt) * SRC + sg] = p[tt];
}

// ---------------------------------------------------------------------------
// Context GEMM + normalization:
// out[b,t,:] = (g_a[b,t,:] @ memory[b]) / sum_q psum[b,t,q]
// ---------------------------------------------------------------------------
__global__ void __launch_bounds__(256) context_kernel(
    const float* __restrict__ memory,
    float* __restrict__ out)
{
    __shared__ float As[64 * 32];
    __shared__ float Bs[32 * 32];

    const int cb  = blockIdx.x;
    const int tb  = blockIdx.y;
    const int b   = blockIdx.z;
    const int tid = threadIdx.x;
    const int col = tid & 31;
    const int tr0 = (tid >> 5) * 8;

    const float* Ab = g_a + (size_t)(b * TGT + tb * 64) * SRC;
    const float* Bb = memory + (size_t)b * SRC * ED + cb * 32;

    const int ar = tid >> 2;
    const int ac = (tid & 3) * 8;
    const int br = tid >> 3;
    const int bc = (tid & 7) * 4;

    float acc[8];
    #pragma unroll
    for (int i = 0; i < 8; i++) acc[i] = 0.f;

    for (int sc = 0; sc < SRC; sc += 32) {
        __syncthreads();
        *(float4*)(As + ar * 32 + ac)     = *(const float4*)(Ab + (size_t)ar * SRC + sc + ac);
        *(float4*)(As + ar * 32 + ac + 4) = *(const float4*)(Ab + (size_t)ar * SRC + sc + ac + 4);
        *(float4*)(Bs + br * 32 + bc)     = *(const float4*)(Bb + (size_t)(sc + br) * ED + bc);
        __syncthreads();

        #pragma unroll
        for (int s = 0; s < 32; s++) {
            float bv = Bs[s * 32 + col];
            #pragma unroll
            for (int i = 0; i < 8; i++)
                acc[i] = fmaf(As[(tr0 + i) * 32 + s], bv, acc[i]);
        }
    }

    #pragma unroll
    for (int i = 0; i < 8; i++) {
        const int t = tb * 64 + tr0 + i;
        const float* ps = g_psum + (b * TGT + t) * 4;
        const float inv = 1.f / (ps[0] + ps[1] + ps[2] + ps[3]);
        out[(size_t)(b * TGT + t) * ED + cb * 32 + col] = acc[i] * inv;
    }
}

// ---------------------------------------------------------------------------
extern "C" void kernel_launch(void* const* d_in, const int* in_sizes, int n_in,
                              void* d_out, int out_size)
{
    const float* memory = (const float*)d_in[0];
    const float* dec    = (const float*)d_in[1];
    const int*   mask   = (const int*)d_in[2];
    const float* Wa     = (const float*)d_in[3];
    const float* Va     = (const float*)d_in[4];
    float*       out    = (float*)d_out;

    (void)in_sizes; (void)n_in; (void)out_size;

    conv_a<<<2560, 256>>>(memory, dec);
    conv_w<<<dim3(16, 16, 2), dim3(32, 8)>>>(Wa);
    gemm_tc<<<dim3(4, 40), 256>>>();
    score_kernel<<<dim3(TGT / TT, 4, BB), 256>>>(Va, mask);
    context_kernel<<<dim3(16, 2, BB), 256>>>(memory, out);
}

// round 13
// speedup vs baseline: 1.0822x; 1.0822x over previous
#include <cuda_runtime.h>
#include <cuda_bf16.h>
#include <cstdint>

#define BB   8
#define SRC  512
#define TGT  128
#define ED   512
#define DD   512
#define TT   4

// Scratch (device globals: allocation-free per harness rules)
// NOTE: g_mp/g_dp hold Eb = exp(2*mp), Ea = exp(2*dp) (written by gemm_tc).
__device__ float g_mp[BB * SRC * DD];          // 8 MB
__device__ float g_dp[BB * TGT * DD];          // 2 MB
__device__ float g_a [BB * TGT * SRC];         // 2 MB: UNNORMALIZED exp(logit)
__device__ float g_psum[BB * TGT * 4];         // per-(b,t,s-quarter) partial sums
__device__ __nv_bfloat16 g_Ah[5120 * 512];     // A hi (memory rows 0..4095, dec 4096..5119)
__device__ __nv_bfloat16 g_Al[5120 * 512];     // A lo
__device__ __nv_bfloat16 g_Wth[2 * 512 * 512]; // W^T hi: sel 0 = Wa_d, 1 = Wa_m; [n][k]
__device__ __nv_bfloat16 g_Wtl[2 * 512 * 512]; // W^T lo

__device__ __forceinline__ float fast_rcp(float x) {
    float y;
    asm("rcp.approx.ftz.f32 %0, %1;" : "=f"(y) : "f"(x));   // bare MUFU.RCP
    return y;
}

__device__ __forceinline__ void cp_async16(void* smem_dst, const void* gmem_src) {
    uint32_t d = (uint32_t)__cvta_generic_to_shared(smem_dst);
    asm volatile("cp.async.ca.shared.global [%0], [%1], 16;\n" :: "r"(d), "l"(gmem_src));
}
#define CP_COMMIT() asm volatile("cp.async.commit_group;\n")
#define CP_WAIT1()  asm volatile("cp.async.wait_group 1;\n")
#define CP_WAIT0()  asm volatile("cp.async.wait_group 0;\n")

__device__ __forceinline__ void ldm_x4(uint32_t* r, uint32_t addr) {
    asm volatile("ldmatrix.sync.aligned.m8n8.x4.shared.b16 {%0,%1,%2,%3}, [%4];"
                 : "=r"(r[0]), "=r"(r[1]), "=r"(r[2]), "=r"(r[3]) : "r"(addr));
}
__device__ __forceinline__ void mma16816(float* c, const uint32_t* a, const uint32_t* b) {
    asm volatile("mma.sync.aligned.m16n8k16.row.col.f32.bf16.bf16.f32 "
                 "{%0,%1,%2,%3}, {%4,%5,%6,%7}, {%8,%9}, {%0,%1,%2,%3};"
                 : "+f"(c[0]), "+f"(c[1]), "+f"(c[2]), "+f"(c[3])
                 : "r"(a[0]), "r"(a[1]), "r"(a[2]), "r"(a[3]), "r"(b[0]), "r"(b[1]));
}

// ---------------------------------------------------------------------------
// Conversion: fp32 -> bf16 (hi, lo) for A = [memory ; dec]  (5120 x 512)
// ---------------------------------------------------------------------------
__global__ void __launch_bounds__(256) conv_a(
    const float* __restrict__ memory, const float* __restrict__ dec)
{
    const int idx = blockIdx.x * 256 + threadIdx.x;          // float4 index
    const float4 v = (idx < 524288) ? ((const float4*)memory)[idx]
                                    : ((const float4*)dec)[idx - 524288];
    float xs[4] = {v.x, v.y, v.z, v.w};
    __nv_bfloat16 h[4], l[4];
    #pragma unroll
    for (int i = 0; i < 4; i++) {
        h[i] = __float2bfloat16(xs[i]);
        l[i] = __float2bfloat16(xs[i] - __bfloat162float(h[i]));
    }
    ((__nv_bfloat162*)g_Ah)[idx * 2]     = __halves2bfloat162(h[0], h[1]);
    ((__nv_bfloat162*)g_Ah)[idx * 2 + 1] = __halves2bfloat162(h[2], h[3]);
    ((__nv_bfloat162*)g_Al)[idx * 2]     = __halves2bfloat162(l[0], l[1]);
    ((__nv_bfloat162*)g_Al)[idx * 2 + 1] = __halves2bfloat162(l[2], l[3]);
}

// ---------------------------------------------------------------------------
// Conversion: W^T hi/lo.  Wt[sel][n][k] = Wa[sel*512 + k][n];  sel 0=Wa_d, 1=Wa_m
// ---------------------------------------------------------------------------
__global__ void __launch_bounds__(256) conv_w(const float* __restrict__ Wa)
{
    __shared__ float s[32][33];
    const int tx = threadIdx.x, ty = threadIdx.y;            // 32 x 8
    const int bx = blockIdx.x, by = blockIdx.y, sel = blockIdx.z;

    #pragma unroll
    for (int j = 0; j < 32; j += 8)
        s[ty + j][tx] = Wa[(size_t)(sel * 512 + by * 32 + ty + j) * 512 + bx * 32 + tx];
    __syncthreads();

    #pragma unroll
    for (int j = 0; j < 32; j += 8) {
        const int n = bx * 32 + ty + j;
        const int k = by * 32 + tx;
        float x = s[tx][ty + j];
        __nv_bfloat16 h = __float2bfloat16(x);
        __nv_bfloat16 l = __float2bfloat16(x - __bfloat162float(h));
        const size_t o = (size_t)(sel * 512 + n) * 512 + k;
        g_Wth[o] = h;
        g_Wtl[o] = l;
    }
}

// ---------------------------------------------------------------------------
// Tensor-core projection GEMM via mma.sync (bf16 3-way split, fp32 accum).
// C tile 128x64 (R11 shape, measured best), grid (8, 40) = 320 CTAs.
// NOW 3 CTAs/SM (36KB smem x3 = 108KB; B-frags loaded per-half to keep regs
// ~75 under the 85-reg cap) -> capacity 444 >= 320: SINGLE WAVE + 24 warps/SM.
// EPILOGUE stores exp(2*proj) for the score kernel's rcp formulation.
// ---------------------------------------------------------------------------
#define PITCH 48
#define OA_H  0
#define OA_L  6144
#define OW_H  12288
#define OW_L  15360
#define BUFSZ 18432

__global__ void __launch_bounds__(256, 3) gemm_tc()
{
    __shared__ char sm[2 * BUFSZ];                // 36 KB
    const uint32_t sb = (uint32_t)__cvta_generic_to_shared(sm);

    const int tid  = threadIdx.x;
    const int lane = tid & 31;
    const int w    = tid >> 5;
    const int wm   = w >> 1;                      // 0..3 (m)
    const int wn   = w & 1;                       // 0..1 (n)
    const int bn   = blockIdx.x;                  // 0..7
    const int by   = blockIdx.y;                  // 0..39

    const int m_base = by * 128;
    const int sel    = (by < 32) ? 1 : 0;
    float* C = (by < 32) ? (g_mp + (size_t)by * 128 * 512)
                         : (g_dp + (size_t)(by - 32) * 128 * 512);
    const __nv_bfloat16* Wh = g_Wth + (size_t)sel * 512 * 512 + (size_t)bn * 64 * 512;
    const __nv_bfloat16* Wl = g_Wtl + (size_t)sel * 512 * 512 + (size_t)bn * 64 * 512;

    const int ar = tid >> 1, ac = tid & 1;
    const int wr = (tid & 127) >> 1, wc = tid & 1;
    const bool do_w = (tid < 128);

    auto issue = [&](int kc, int buf) {
        char* B = sm + buf * BUFSZ;
        const size_t asrc = (size_t)(m_base + ar) * 512 + kc * 16 + ac * 8;
        cp_async16(B + OA_H + ar * PITCH + ac * 16, g_Ah + asrc);
        cp_async16(B + OA_L + ar * PITCH + ac * 16, g_Al + asrc);
        if (do_w) {
            const size_t wsrc = (size_t)wr * 512 + kc * 16 + wc * 8;
            cp_async16(B + OW_H + wr * PITCH + wc * 16, Wh + wsrc);
            cp_async16(B + OW_L + wr * PITCH + wc * 16, Wl + wsrc);
        }
        CP_COMMIT();
    };

    const uint32_t a_off = (uint32_t)((wm * 32 + (lane & 15)) * PITCH + (lane >> 4) * 16);
    const uint32_t b_off = (uint32_t)((wn * 32 + (lane & 7) + ((lane >> 4) * 8)) * PITCH
                                      + (((lane >> 3) & 1) * 16));

    float acc[2][4][4];
    #pragma unroll
    for (int i = 0; i < 2; i++)
        #pragma unroll
        for (int j = 0; j < 4; j++)
            #pragma unroll
            for (int e = 0; e < 4; e++) acc[i][j][e] = 0.f;

    issue(0, 0);

    for (int kc = 0; kc < 32; kc++) {
        if (kc < 31) { issue(kc + 1, (kc + 1) & 1); CP_WAIT1(); }
        else         { CP_WAIT0(); }
        __syncthreads();

        const uint32_t base = sb + (kc & 1) * BUFSZ;
        uint32_t ah[2][4], al[2][4];
        #pragma unroll
        for (int i = 0; i < 2; i++) {
            ldm_x4(ah[i], base + OA_H + a_off + i * 16 * PITCH);
            ldm_x4(al[i], base + OA_L + a_off + i * 16 * PITCH);
        }

        #pragma unroll
        for (int jb = 0; jb < 2; jb++) {           // B-frags per-half: live 16 regs
            uint32_t bh[4], bl[4];
            ldm_x4(bh, base + OW_H + b_off + jb * 16 * PITCH);
            ldm_x4(bl, base + OW_L + b_off + jb * 16 * PITCH);
            #pragma unroll
            for (int h = 0; h < 2; h++) {
                const int j = jb * 2 + h;
                const uint32_t* ph = &bh[2 * h];
                const uint32_t* pl = &bl[2 * h];
                #pragma unroll
                for (int i = 0; i < 2; i++) {
                    mma16816(acc[i][j], ah[i], ph);
                    mma16816(acc[i][j], ah[i], pl);
                    mma16816(acc[i][j], al[i], ph);
                }
            }
        }
        __syncthreads();
    }

    // epilogue: store E = exp(2 * proj)
    #pragma unroll
    for (int i = 0; i < 2; i++) {
        const int r0 = wm * 32 + i * 16 + (lane >> 2);
        #pragma unroll
        for (int j = 0; j < 4; j++) {
            const int c0 = bn * 64 + wn * 32 + j * 8 + (lane & 3) * 2;
            *(float2*)(C + (size_t)r0 * 512 + c0) =
                make_float2(__expf(2.f * acc[i][j][0]), __expf(2.f * acc[i][j][1]));
            *(float2*)(C + (size_t)(r0 + 8) * 512 + c0) =
                make_float2(__expf(2.f * acc[i][j][2]), __expf(2.f * acc[i][j][3]));
        }
    }
}

// ---------------------------------------------------------------------------
// Score -> unnormalized p = exp(e) in g_a + per-quarter partial sums g_psum.
// e[t,s] = -2 * sum_k Va_k / (1 + Ea[t,k]*Eb[s,k])  (+const, cancels in
// softmax; |e| bounded ~36 -> exp safe in fp32, no max pass).
// Grid (TGT/TT, 4 s-quarters, BB) = 1024 blocks; tile 128 x 32, cp.async
// double-buffered; 4 blocks/SM.
// ---------------------------------------------------------------------------
#define STW (128 * 36)

__global__ void __launch_bounds__(256, 4) score_kernel(
    const float* __restrict__ Va,
    const int* __restrict__ mask)
{
    __shared__ float s_mp[2 * STW];     // 36 KB
    __shared__ float s_dp[TT * 512];    //  8 KB
    __shared__ float s_va[512];         //  2 KB
    __shared__ float s_red[TT * 4];

    const int b    = blockIdx.z;
    const int q4   = blockIdx.y;        // s-quarter 0..3
    const int t0   = blockIdx.x * TT;
    const int tid  = threadIdx.x;
    const int lane = tid & 31;
    const int w    = tid >> 5;
    const int wr4  = w & 3;             // row-group
    const int tg   = (w >> 2) * 2;      // t-pair base

    {
        const float4* dpg = (const float4*)(g_dp + (size_t)(b * TGT + t0) * 512);
        ((float4*)s_dp)[tid]       = dpg[tid];
        ((float4*)s_dp)[tid + 256] = dpg[tid + 256];
        if (tid < 128) ((float4*)s_va)[tid] = ((const float4*)Va)[tid];
    }

    const float* mpg = g_mp + (size_t)(b * SRC + q4 * 128) * 512;

    // loader: 1024 float4 per chunk, 4 per thread
    const int lr[4] = { (tid + 0) >> 3, (tid + 256) >> 3, (tid + 512) >> 3, (tid + 768) >> 3 };
    const int lc4   = (tid & 7) << 2;

    auto issue = [&](int kc, int buf) {
        float* dst = s_mp + buf * STW;
        const float* src = mpg + kc * 32;
        #pragma unroll
        for (int i = 0; i < 4; i++)
            cp_async16(dst + lr[i] * 36 + lc4, src + (size_t)lr[i] * 512 + lc4);
        CP_COMMIT();
    };

    issue(0, 0);

    float acc[2] = {0.f, 0.f};
    const int myrow = wr4 * 32 + lane;

    for (int c = 0; c < 16; c++) {
        if (c < 15) { issue(c + 1, (c + 1) & 1); CP_WAIT1(); }
        else        { CP_WAIT0(); }
        __syncthreads();

        const float* mrow_s = s_mp + (c & 1) * STW + myrow * 36;
        const int kc = c * 32;
        #pragma unroll
        for (int k = 0; k < 32; k += 4) {
            float4 m4 = *(const float4*)(mrow_s + k);           // Eb
            float4 v4 = *(const float4*)(s_va + kc + k);
            #pragma unroll
            for (int tt = 0; tt < 2; tt++) {
                float4 d4 = *(const float4*)(s_dp + (tg + tt) * 512 + kc + k);  // Ea
                float r0v = fast_rcp(fmaf(d4.x, m4.x, 1.f));
                float r1v = fast_rcp(fmaf(d4.y, m4.y, 1.f));
                float r2v = fast_rcp(fmaf(d4.z, m4.z, 1.f));
                float r3v = fast_rcp(fmaf(d4.w, m4.w, 1.f));
                acc[tt] = fmaf(v4.x, r0v, acc[tt]);
                acc[tt] = fmaf(v4.y, r1v, acc[tt]);
                acc[tt] = fmaf(v4.z, r2v, acc[tt]);
                acc[tt] = fmaf(v4.w, r3v, acc[tt]);
            }
        }
        __syncthreads();   // compute done before buffer refilled
    }

    // p = exp(-2*acc), masked to 0
    const int sg = q4 * 128 + myrow;
    const bool mok = (mask[b * SRC + sg] != 0);
    float p[2];
    #pragma unroll
    for (int tt = 0; tt < 2; tt++)
        p[tt] = mok ? __expf(-2.f * acc[tt]) : 0.f;

    // per-t partial sums over this block's 128 s (4 warps share each t)
    #pragma unroll
    for (int tt = 0; tt < 2; tt++) {
        float s = p[tt];
        #pragma unroll
        for (int o = 16; o; o >>= 1) s += __shfl_xor_sync(0xffffffffu, s, o);
        if (lane == 0) s_red[(tg + tt) * 4 + wr4] = s;
    }
    __syncthreads();
    if (tid < TT) {
        const float* r = s_red + tid * 4;
        g_psum[(b * TGT + t0 + tid) * 4 + q4] = r[0] + r[1] + r[2] + r[3];
    }

    #pragma unroll
    for (int tt = 0; tt < 2; tt++)
        g_a[(size_t)(b * TGT + t0 + tg + tt) * SRC + sg] = p[tt];
}

// ---------------------------------------------------------------------------
// Context GEMM + normalization:
// out[b,t,:] = (g_a[b,t,:] @ memory[b]) / sum_q psum[b,t,q]
// ---------------------------------------------------------------------------
__global__ void __launch_bounds__(256) context_kernel(
    const float* __restrict__ memory,
    float* __restrict__ out)
{
    __shared__ float As[64 * 32];
    __shared__ float Bs[32 * 32];

    const int cb  = blockIdx.x;
    const int tb  = blockIdx.y;
    const int b   = blockIdx.z;
    const int tid = threadIdx.x;
    const int col = tid & 31;
    const int tr0 = (tid >> 5) * 8;

    const float* Ab = g_a + (size_t)(b * TGT + tb * 64) * SRC;
    const float* Bb = memory + (size_t)b * SRC * ED + cb * 32;

    const int ar = tid >> 2;
    const int ac = (tid & 3) * 8;
    const int br = tid >> 3;
    const int bc = (tid & 7) * 4;

    float acc[8];
    #pragma unroll
    for (int i = 0; i < 8; i++) acc[i] = 0.f;

    for (int sc = 0; sc < SRC; sc += 32) {
        __syncthreads();
        *(float4*)(As + ar * 32 + ac)     = *(const float4*)(Ab + (size_t)ar * SRC + sc + ac);
        *(float4*)(As + ar * 32 + ac + 4) = *(const float4*)(Ab + (size_t)ar * SRC + sc + ac + 4);
        *(float4*)(Bs + br * 32 + bc)     = *(const float4*)(Bb + (size_t)(sc + br) * ED + bc);
        __syncthreads();

        #pragma unroll
        for (int s = 0; s < 32; s++) {
            float bv = Bs[s * 32 + col];
            #pragma unroll
            for (int i = 0; i < 8; i++)
                acc[i] = fmaf(As[(tr0 + i) * 32 + s], bv, acc[i]);
        }
    }

    #pragma unroll
    for (int i = 0; i < 8; i++) {
        const int t = tb * 64 + tr0 + i;
        const float* ps = g_psum + (b * TGT + t) * 4;
        const float inv = 1.f / (ps[0] + ps[1] + ps[2] + ps[3]);
        out[(size_t)(b * TGT + t) * ED + cb * 32 + col] = acc[i] * inv;
    }
}

// ---------------------------------------------------------------------------
extern "C" void kernel_launch(void* const* d_in, const int* in_sizes, int n_in,
                              void* d_out, int out_size)
{
    const float* memory = (const float*)d_in[0];
    const float* dec    = (const float*)d_in[1];
    const int*   mask   = (const int*)d_in[2];
    const float* Wa     = (const float*)d_in[3];
    const float* Va     = (const float*)d_in[4];
    float*       out    = (float*)d_out;

    (void)in_sizes; (void)n_in; (void)out_size;

    conv_a<<<2560, 256>>>(memory, dec);
    conv_w<<<dim3(16, 16, 2), dim3(32, 8)>>>(Wa);
    gemm_tc<<<dim3(8, 40), 256>>>();
    score_kernel<<<dim3(TGT / TT, 4, BB), 256>>>(Va, mask);
    context_kernel<<<dim3(16, 2, BB), 256>>>(memory, out);
}

// round 14
// speedup vs baseline: 1.0941x; 1.0110x over previous
#include <cuda_runtime.h>
#include <cuda_fp16.h>
#include <cstdint>

#define BB   8
#define SRC  512
#define TGT  128
#define ED   512
#define DD   512
#define TT   4

// Scratch (device globals: allocation-free per harness rules)
// NOTE: g_mp/g_dp hold Eb = exp(2*mp), Ea = exp(2*dp) (written by gemm_tc).
__device__ float g_mp[BB * SRC * DD];          // 8 MB
__device__ float g_dp[BB * TGT * DD];          // 2 MB
__device__ float g_a [BB * TGT * SRC];         // 2 MB: UNNORMALIZED exp(logit)
__device__ float g_psum[BB * TGT * 4];         // per-(b,t,s-quarter) partial sums
__device__ __half g_Ah[5120 * 512];            // A hi fp16 (memory rows 0..4095, dec 4096..5119)
__device__ __half g_Al[5120 * 512];            // A lo fp16 (A = Ah + Al to ~2^-22)
__device__ __half g_Wt[2 * 512 * 512];         // W^T fp16: sel 0 = Wa_d, 1 = Wa_m; [n][k]

__device__ __forceinline__ float fast_rcp(float x) {
    float y;
    asm("rcp.approx.ftz.f32 %0, %1;" : "=f"(y) : "f"(x));   // bare MUFU.RCP
    return y;
}

__device__ __forceinline__ void cp_async16(void* smem_dst, const void* gmem_src) {
    uint32_t d = (uint32_t)__cvta_generic_to_shared(smem_dst);
    asm volatile("cp.async.ca.shared.global [%0], [%1], 16;\n" :: "r"(d), "l"(gmem_src));
}
#define CP_COMMIT() asm volatile("cp.async.commit_group;\n")
#define CP_WAIT1()  asm volatile("cp.async.wait_group 1;\n")
#define CP_WAIT0()  asm volatile("cp.async.wait_group 0;\n")

__device__ __forceinline__ void ldm_x4(uint32_t* r, uint32_t addr) {
    asm volatile("ldmatrix.sync.aligned.m8n8.x4.shared.b16 {%0,%1,%2,%3}, [%4];"
                 : "=r"(r[0]), "=r"(r[1]), "=r"(r[2]), "=r"(r[3]) : "r"(addr));
}
__device__ __forceinline__ void mma16816_f16(float* c, const uint32_t* a, const uint32_t* b) {
    asm volatile("mma.sync.aligned.m16n8k16.row.col.f32.f16.f16.f32 "
                 "{%0,%1,%2,%3}, {%4,%5,%6,%7}, {%8,%9}, {%0,%1,%2,%3};"
                 : "+f"(c[0]), "+f"(c[1]), "+f"(c[2]), "+f"(c[3])
                 : "r"(a[0]), "r"(a[1]), "r"(a[2]), "r"(a[3]), "r"(b[0]), "r"(b[1]));
}

// ---------------------------------------------------------------------------
// Conversion: fp32 -> fp16 (hi, lo) for A = [memory ; dec]  (5120 x 512)
// ---------------------------------------------------------------------------
__global__ void __launch_bounds__(256) conv_a(
    const float* __restrict__ memory, const float* __restrict__ dec)
{
    const int idx = blockIdx.x * 256 + threadIdx.x;          // float4 index
    const float4 v = (idx < 524288) ? ((const float4*)memory)[idx]
                                    : ((const float4*)dec)[idx - 524288];
    float xs[4] = {v.x, v.y, v.z, v.w};
    __half h[4], l[4];
    #pragma unroll
    for (int i = 0; i < 4; i++) {
        h[i] = __float2half(xs[i]);
        l[i] = __float2half(xs[i] - __half2float(h[i]));
    }
    ((__half2*)g_Ah)[idx * 2]     = __halves2half2(h[0], h[1]);
    ((__half2*)g_Ah)[idx * 2 + 1] = __halves2half2(h[2], h[3]);
    ((__half2*)g_Al)[idx * 2]     = __halves2half2(l[0], l[1]);
    ((__half2*)g_Al)[idx * 2 + 1] = __halves2half2(l[2], l[3]);
}

// ---------------------------------------------------------------------------
// Conversion: W^T fp16.  Wt[sel][n][k] = Wa[sel*512 + k][n];  sel 0=Wa_d, 1=Wa_m
// ---------------------------------------------------------------------------
__global__ void __launch_bounds__(256) conv_w(const float* __restrict__ Wa)
{
    __shared__ float s[32][33];
    const int tx = threadIdx.x, ty = threadIdx.y;            // 32 x 8
    const int bx = blockIdx.x, by = blockIdx.y, sel = blockIdx.z;

    #pragma unroll
    for (int j = 0; j < 32; j += 8)
        s[ty + j][tx] = Wa[(size_t)(sel * 512 + by * 32 + ty + j) * 512 + bx * 32 + tx];
    __syncthreads();

    #pragma unroll
    for (int j = 0; j < 32; j += 8) {
        const int n = bx * 32 + ty + j;
        const int k = by * 32 + tx;
        g_Wt[(size_t)(sel * 512 + n) * 512 + k] = __float2half(s[tx][ty + j]);
    }
}

// ---------------------------------------------------------------------------
// Tensor-core projection GEMM via mma.sync (fp16 2-way A-split, fp32 accum).
// C = Ah*W + Al*W with Ah,Al fp16 (A exact to ~2^-22), W single fp16
// (sole error source, logit err ~1e-4 << 1e-3 gate).
// C tile 128x64, grid (8,40)=320 CTAs, 3 CTAs/SM -> single wave.
// Per k16-chunk/warp: 6 ldmatrix.x4 + 16 mma (was 8 + 24 with 3-split bf16).
// EPILOGUE stores exp(2*proj) for the score kernel's rcp formulation.
// ---------------------------------------------------------------------------
#define PITCH 48
#define OA_H  0
#define OA_L  6144
#define OW_H  12288
#define BUFSZ 15360

__global__ void __launch_bounds__(256, 3) gemm_tc()
{
    __shared__ char sm[2 * BUFSZ];                // 30 KB
    const uint32_t sb = (uint32_t)__cvta_generic_to_shared(sm);

    const int tid  = threadIdx.x;
    const int lane = tid & 31;
    const int w    = tid >> 5;
    const int wm   = w >> 1;                      // 0..3 (m)
    const int wn   = w & 1;                       // 0..1 (n)
    const int bn   = blockIdx.x;                  // 0..7
    const int by   = blockIdx.y;                  // 0..39

    const int m_base = by * 128;
    const int sel    = (by < 32) ? 1 : 0;
    float* C = (by < 32) ? (g_mp + (size_t)by * 128 * 512)
                         : (g_dp + (size_t)(by - 32) * 128 * 512);
    const __half* Wp = g_Wt + (size_t)sel * 512 * 512 + (size_t)bn * 64 * 512;

    const int ar = tid >> 1, ac = tid & 1;
    const int wr = (tid & 127) >> 1, wc = tid & 1;
    const bool do_w = (tid < 128);

    auto issue = [&](int kc, int buf) {
        char* B = sm + buf * BUFSZ;
        const size_t asrc = (size_t)(m_base + ar) * 512 + kc * 16 + ac * 8;
        cp_async16(B + OA_H + ar * PITCH + ac * 16, g_Ah + asrc);
        cp_async16(B + OA_L + ar * PITCH + ac * 16, g_Al + asrc);
        if (do_w) {
            const size_t wsrc = (size_t)wr * 512 + kc * 16 + wc * 8;
            cp_async16(B + OW_H + wr * PITCH + wc * 16, Wp + wsrc);
        }
        CP_COMMIT();
    };

    const uint32_t a_off = (uint32_t)((wm * 32 + (lane & 15)) * PITCH + (lane >> 4) * 16);
    const uint32_t b_off = (uint32_t)((wn * 32 + (lane & 7) + ((lane >> 4) * 8)) * PITCH
                                      + (((lane >> 3) & 1) * 16));

    float acc[2][4][4];
    #pragma unroll
    for (int i = 0; i < 2; i++)
        #pragma unroll
        for (int j = 0; j < 4; j++)
            #pragma unroll
            for (int e = 0; e < 4; e++) acc[i][j][e] = 0.f;

    issue(0, 0);

    for (int kc = 0; kc < 32; kc++) {
        if (kc < 31) { issue(kc + 1, (kc + 1) & 1); CP_WAIT1(); }
        else         { CP_WAIT0(); }
        __syncthreads();

        const uint32_t base = sb + (kc & 1) * BUFSZ;
        uint32_t ah[2][4], al[2][4];
        #pragma unroll
        for (int i = 0; i < 2; i++) {
            ldm_x4(ah[i], base + OA_H + a_off + i * 16 * PITCH);
            ldm_x4(al[i], base + OA_L + a_off + i * 16 * PITCH);
        }

        #pragma unroll
        for (int jb = 0; jb < 2; jb++) {
            uint32_t bh[4];
            ldm_x4(bh, base + OW_H + b_off + jb * 16 * PITCH);
            #pragma unroll
            for (int h = 0; h < 2; h++) {
                const int j = jb * 2 + h;
                const uint32_t* ph = &bh[2 * h];
                #pragma unroll
                for (int i = 0; i < 2; i++) {
                    mma16816_f16(acc[i][j], ah[i], ph);
                    mma16816_f16(acc[i][j], al[i], ph);
                }
            }
        }
        __syncthreads();
    }

    // epilogue: store E = exp(2 * proj)
    #pragma unroll
    for (int i = 0; i < 2; i++) {
        const int r0 = wm * 32 + i * 16 + (lane >> 2);
        #pragma unroll
        for (int j = 0; j < 4; j++) {
            const int c0 = bn * 64 + wn * 32 + j * 8 + (lane & 3) * 2;
            *(float2*)(C + (size_t)r0 * 512 + c0) =
                make_float2(__expf(2.f * acc[i][j][0]), __expf(2.f * acc[i][j][1]));
            *(float2*)(C + (size_t)(r0 + 8) * 512 + c0) =
                make_float2(__expf(2.f * acc[i][j][2]), __expf(2.f * acc[i][j][3]));
        }
    }
}

// ---------------------------------------------------------------------------
// Score -> unnormalized p = exp(e) in g_a + per-quarter partial sums g_psum.
// e[t,s] = -2 * sum_k Va_k / (1 + Ea[t,k]*Eb[s,k])  (+const, cancels in
// softmax; |e| bounded ~36 -> exp safe in fp32, no max pass).
// Grid (TGT/TT, 4 s-quarters, BB) = 1024 blocks; tile 128 x 32, cp.async
// double-buffered; 4 blocks/SM.
// ---------------------------------------------------------------------------
#define STW (128 * 36)

__global__ void __launch_bounds__(256, 4) score_kernel(
    const float* __restrict__ Va,
    const int* __restrict__ mask)
{
    __shared__ float s_mp[2 * STW];     // 36 KB
    __shared__ float s_dp[TT * 512];    //  8 KB
    __shared__ float s_va[512];         //  2 KB
    __shared__ float s_red[TT * 4];

    const int b    = blockIdx.z;
    const int q4   = blockIdx.y;        // s-quarter 0..3
    const int t0   = blockIdx.x * TT;
    const int tid  = threadIdx.x;
    const int lane = tid & 31;
    const int w    = tid >> 5;
    const int wr4  = w & 3;             // row-group
    const int tg   = (w >> 2) * 2;      // t-pair base

    {
        const float4* dpg = (const float4*)(g_dp + (size_t)(b * TGT + t0) * 512);
        ((float4*)s_dp)[tid]       = dpg[tid];
        ((float4*)s_dp)[tid + 256] = dpg[tid + 256];
        if (tid < 128) ((float4*)s_va)[tid] = ((const float4*)Va)[tid];
    }

    const float* mpg = g_mp + (size_t)(b * SRC + q4 * 128) * 512;

    // loader: 1024 float4 per chunk, 4 per thread
    const int lr[4] = { (tid + 0) >> 3, (tid + 256) >> 3, (tid + 512) >> 3, (tid + 768) >> 3 };
    const int lc4   = (tid & 7) << 2;

    auto issue = [&](int kc, int buf) {
        float* dst = s_mp + buf * STW;
        const float* src = mpg + kc * 32;
        #pragma unroll
        for (int i = 0; i < 4; i++)
            cp_async16(dst + lr[i] * 36 + lc4, src + (size_t)lr[i] * 512 + lc4);
        CP_COMMIT();
    };

    issue(0, 0);

    float acc[2] = {0.f, 0.f};
    const int myrow = wr4 * 32 + lane;

    for (int c = 0; c < 16; c++) {
        if (c < 15) { issue(c + 1, (c + 1) & 1); CP_WAIT1(); }
        else        { CP_WAIT0(); }
        __syncthreads();

        const float* mrow_s = s_mp + (c & 1) * STW + myrow * 36;
        const int kc = c * 32;
        #pragma unroll
        for (int k = 0; k < 32; k += 4) {
            float4 m4 = *(const float4*)(mrow_s + k);           // Eb
            float4 v4 = *(const float4*)(s_va + kc + k);
            #pragma unroll
            for (int tt = 0; tt < 2; tt++) {
                float4 d4 = *(const float4*)(s_dp + (tg + tt) * 512 + kc + k);  // Ea
                float r0v = fast_rcp(fmaf(d4.x, m4.x, 1.f));
                float r1v = fast_rcp(fmaf(d4.y, m4.y, 1.f));
                float r2v = fast_rcp(fmaf(d4.z, m4.z, 1.f));
                float r3v = fast_rcp(fmaf(d4.w, m4.w, 1.f));
                acc[tt] = fmaf(v4.x, r0v, acc[tt]);
                acc[tt] = fmaf(v4.y, r1v, acc[tt]);
                acc[tt] = fmaf(v4.z, r2v, acc[tt]);
                acc[tt] = fmaf(v4.w, r3v, acc[tt]);
            }
        }
        __syncthreads();   // compute done before buffer refilled
    }

    // p = exp(-2*acc), masked to 0
    const int sg = q4 * 128 + myrow;
    const bool mok = (mask[b * SRC + sg] != 0);
    float p[2];
    #pragma unroll
    for (int tt = 0; tt < 2; tt++)
        p[tt] = mok ? __expf(-2.f * acc[tt]) : 0.f;

    // per-t partial sums over this block's 128 s (4 warps share each t)
    #pragma unroll
    for (int tt = 0; tt < 2; tt++) {
        float s = p[tt];
        #pragma unroll
        for (int o = 16; o; o >>= 1) s += __shfl_xor_sync(0xffffffffu, s, o);
        if (lane == 0) s_red[(tg + tt) * 4 + wr4] = s;
    }
    __syncthreads();
    if (tid < TT) {
        const float* r = s_red + tid * 4;
        g_psum[(b * TGT + t0 + tid) * 4 + q4] = r[0] + r[1] + r[2] + r[3];
    }

    #pragma unroll
    for (int tt = 0; tt < 2; tt++)
        g_a[(size_t)(b * TGT + t0 + tg + tt) * SRC + sg] = p[tt];
}

// ---------------------------------------------------------------------------
// Context GEMM + normalization:
// out[b,t,:] = (g_a[b,t,:] @ memory[b]) / sum_q psum[b,t,q]
// ---------------------------------------------------------------------------
__global__ void __launch_bounds__(256) context_kernel(
    const float* __restrict__ memory,
    float* __restrict__ out)
{
    __shared__ float As[64 * 32];
    __shared__ float Bs[32 * 32];

    const int cb  = blockIdx.x;
    const int tb  = blockIdx.y;
    const int b   = blockIdx.z;
    const int tid = threadIdx.x;
    const int col = tid & 31;
    const int tr0 = (tid >> 5) * 8;

    const float* Ab = g_a + (size_t)(b * TGT + tb * 64) * SRC;
    const float* Bb = memory + (size_t)b * SRC * ED + cb * 32;

    const int ar = tid >> 2;
    const int ac = (tid & 3) * 8;
    const int br = tid >> 3;
    const int bc = (tid & 7) * 4;

    float acc[8];
    #pragma unroll
    for (int i = 0; i < 8; i++) acc[i] = 0.f;

    for (int sc = 0; sc < SRC; sc += 32) {
        __syncthreads();
        *(float4*)(As + ar * 32 + ac)     = *(const float4*)(Ab + (size_t)ar * SRC + sc + ac);
        *(float4*)(As + ar * 32 + ac + 4) = *(const float4*)(Ab + (size_t)ar * SRC + sc + ac + 4);
        *(float4*)(Bs + br * 32 + bc)     = *(const float4*)(Bb + (size_t)(sc + br) * ED + bc);
        __syncthreads();

        #pragma unroll
        for (int s = 0; s < 32; s++) {
            float bv = Bs[s * 32 + col];
            #pragma unroll
            for (int i = 0; i < 8; i++)
                acc[i] = fmaf(As[(tr0 + i) * 32 + s], bv, acc[i]);
        }
    }

    #pragma unroll
    for (int i = 0; i < 8; i++) {
        const int t = tb * 64 + tr0 + i;
        const float* ps = g_psum + (b * TGT + t) * 4;
        const float inv = 1.f / (ps[0] + ps[1] + ps[2] + ps[3]);
        out[(size_t)(b * TGT + t) * ED + cb * 32 + col] = acc[i] * inv;
    }
}

// ---------------------------------------------------------------------------
extern "C" void kernel_launch(void* const* d_in, const int* in_sizes, int n_in,
                              void* d_out, int out_size)
{
    const float* memory = (const float*)d_in[0];
    const float* dec    = (const float*)d_in[1];
    const int*   mask   = (const int*)d_in[2];
    const float* Wa     = (const float*)d_in[3];
    const float* Va     = (const float*)d_in[4];
    float*       out    = (float*)d_out;

    (void)in_sizes; (void)n_in; (void)out_size;

    conv_a<<<2560, 256>>>(memory, dec);
    conv_w<<<dim3(16, 16, 2), dim3(32, 8)>>>(Wa);
    gemm_tc<<<dim3(8, 40), 256>>>();
    score_kernel<<<dim3(TGT / TT, 4, BB), 256>>>(Va, mask);
    context_kernel<<<dim3(16, 2, BB), 256>>>(memory, out);
}

// round 15
// speedup vs baseline: 1.2880x; 1.1772x over previous
#include <cuda_runtime.h>
#include <cuda_fp16.h>
#include <cstdint>

#define BB   8
#define SRC  512
#define TGT  128
#define ED   512
#define DD   512
#define TT   4

// Scratch (device globals: allocation-free per harness rules)
// NOTE: g_mp/g_dp hold Eb = exp(2*mp), Ea = exp(2*dp) (written by gemm_tc).
__device__ float g_mp[BB * SRC * DD];          // 8 MB
__device__ float g_dp[BB * TGT * DD];          // 2 MB
__device__ float g_a [BB * TGT * SRC];         // 2 MB: UNNORMALIZED exp(logit)
__device__ float g_psum[BB * TGT * 4];         // per-(b,t,s-quarter) partial sums
__device__ __half g_Ah[5120 * 512];            // A fp16 (memory rows 0..4095, dec 4096..5119)
__device__ __half g_Wt[2 * 512 * 512];         // W^T fp16: sel 0 = Wa_d, 1 = Wa_m; [n][k]

__device__ __forceinline__ float fast_rcp(float x) {
    float y;
    asm("rcp.approx.ftz.f32 %0, %1;" : "=f"(y) : "f"(x));   // bare MUFU.RCP
    return y;
}

__device__ __forceinline__ void cp_async16(void* smem_dst, const void* gmem_src) {
    uint32_t d = (uint32_t)__cvta_generic_to_shared(smem_dst);
    asm volatile("cp.async.ca.shared.global [%0], [%1], 16;\n" :: "r"(d), "l"(gmem_src));
}
#define CP_COMMIT() asm volatile("cp.async.commit_group;\n")
#define CP_WAIT1()  asm volatile("cp.async.wait_group 1;\n")
#define CP_WAIT0()  asm volatile("cp.async.wait_group 0;\n")

__device__ __forceinline__ void ldm_x4(uint32_t* r, uint32_t addr) {
    asm volatile("ldmatrix.sync.aligned.m8n8.x4.shared.b16 {%0,%1,%2,%3}, [%4];"
                 : "=r"(r[0]), "=r"(r[1]), "=r"(r[2]), "=r"(r[3]) : "r"(addr));
}
__device__ __forceinline__ void mma16816_f16(float* c, const uint32_t* a, const uint32_t* b) {
    asm volatile("mma.sync.aligned.m16n8k16.row.col.f32.f16.f16.f32 "
                 "{%0,%1,%2,%3}, {%4,%5,%6,%7}, {%8,%9}, {%0,%1,%2,%3};"
                 : "+f"(c[0]), "+f"(c[1]), "+f"(c[2]), "+f"(c[3])
                 : "r"(a[0]), "r"(a[1]), "r"(a[2]), "r"(a[3]), "r"(b[0]), "r"(b[1]));
}

// ---------------------------------------------------------------------------
// Conversion: fp32 -> fp16 for A = [memory ; dec]  (5120 x 512)
// ---------------------------------------------------------------------------
__global__ void __launch_bounds__(256) conv_a(
    const float* __restrict__ memory, const float* __restrict__ dec)
{
    const int idx = blockIdx.x * 256 + threadIdx.x;          // float4 index
    const float4 v = (idx < 524288) ? ((const float4*)memory)[idx]
                                    : ((const float4*)dec)[idx - 524288];
    ((__half2*)g_Ah)[idx * 2]     = __halves2half2(__float2half(v.x), __float2half(v.y));
    ((__half2*)g_Ah)[idx * 2 + 1] = __halves2half2(__float2half(v.z), __float2half(v.w));
}

// ---------------------------------------------------------------------------
// Conversion: W^T fp16.  Wt[sel][n][k] = Wa[sel*512 + k][n];  sel 0=Wa_d, 1=Wa_m
// ---------------------------------------------------------------------------
__global__ void __launch_bounds__(256) conv_w(const float* __restrict__ Wa)
{
    __shared__ float s[32][33];
    const int tx = threadIdx.x, ty = threadIdx.y;            // 32 x 8
    const int bx = blockIdx.x, by = blockIdx.y, sel = blockIdx.z;

    #pragma unroll
    for (int j = 0; j < 32; j += 8)
        s[ty + j][tx] = Wa[(size_t)(sel * 512 + by * 32 + ty + j) * 512 + bx * 32 + tx];
    __syncthreads();

    #pragma unroll
    for (int j = 0; j < 32; j += 8) {
        const int n = bx * 32 + ty + j;
        const int k = by * 32 + tx;
        g_Wt[(size_t)(sel * 512 + n) * 512 + k] = __float2half(s[tx][ty + j]);
    }
}

// ---------------------------------------------------------------------------
// Tensor-core projection GEMM via mma.sync (single fp16, fp32 accum).
// Error: A and W each one fp16 rounding -> logit err ~1.7e-4 (6x under gate;
// R14 measured 1.2e-4 with W-only rounding).
// C tile 128x64, grid (8,40)=320 CTAs, 3 CTAs/SM -> single wave.
// K-chunks of 32 (16 iterations, HALF the barriers of R14); pitch 80B:
// ldmatrix 16B-phase banks 5r+s mod 8 distinct -> conflict-free.
// Per k32-iter/warp: 8 ldmatrix.x4 + 16 mma (R14: 12 + 32 per same k).
// EPILOGUE stores exp(2*proj) for the score kernel's rcp formulation.
// ---------------------------------------------------------------------------
#define PITCH 80
#define OA    0
#define OW    10240
#define BUFSZ 15360

__global__ void __launch_bounds__(256, 3) gemm_tc()
{
    __shared__ char sm[2 * BUFSZ];                // 30 KB
    const uint32_t sb = (uint32_t)__cvta_generic_to_shared(sm);

    const int tid  = threadIdx.x;
    const int lane = tid & 31;
    const int w    = tid >> 5;
    const int wm   = w >> 1;                      // 0..3 (m)
    const int wn   = w & 1;                       // 0..1 (n)
    const int bn   = blockIdx.x;                  // 0..7
    const int by   = blockIdx.y;                  // 0..39

    const int m_base = by * 128;
    const int sel    = (by < 32) ? 1 : 0;
    float* C = (by < 32) ? (g_mp + (size_t)by * 128 * 512)
                         : (g_dp + (size_t)(by - 32) * 128 * 512);
    const __half* Wp = g_Wt + (size_t)sel * 512 * 512 + (size_t)bn * 64 * 512;

    // loaders (k-chunk = 32 halfs = 64B = 4 x 16B segs per row)
    const int arow = tid >> 2;                    // 0..63 (+64 for 2nd half)
    const int aseg = tid & 3;
    auto issue = [&](int kc, int buf) {
        char* B = sm + buf * BUFSZ;
        const size_t koff = (size_t)kc * 32 + aseg * 8;
        cp_async16(B + OA + arow * PITCH + aseg * 16,
                   g_Ah + (size_t)(m_base + arow) * 512 + koff);
        cp_async16(B + OA + (arow + 64) * PITCH + aseg * 16,
                   g_Ah + (size_t)(m_base + arow + 64) * 512 + koff);
        cp_async16(B + OW + arow * PITCH + aseg * 16,
                   Wp + (size_t)arow * 512 + koff);
        CP_COMMIT();
    };

    // ldmatrix base offsets (+ kk*32 selects k16 sub-chunk)
    const uint32_t a_off = (uint32_t)((wm * 32 + (lane & 15)) * PITCH + (lane >> 4) * 16);
    const uint32_t b_off = (uint32_t)((wn * 32 + (lane & 7) + ((lane >> 4) * 8)) * PITCH
                                      + (((lane >> 3) & 1) * 16));

    float acc[2][4][4];
    #pragma unroll
    for (int i = 0; i < 2; i++)
        #pragma unroll
        for (int j = 0; j < 4; j++)
            #pragma unroll
            for (int e = 0; e < 4; e++) acc[i][j][e] = 0.f;

    issue(0, 0);

    for (int kc = 0; kc < 16; kc++) {
        if (kc < 15) { issue(kc + 1, (kc + 1) & 1); CP_WAIT1(); }
        else         { CP_WAIT0(); }
        __syncthreads();

        const uint32_t base = sb + (kc & 1) * BUFSZ;
        #pragma unroll
        for (int kk = 0; kk < 2; kk++) {          // two k16 sub-chunks
            const uint32_t ko = kk * 32;
            uint32_t ah[2][4];
            #pragma unroll
            for (int i = 0; i < 2; i++)
                ldm_x4(ah[i], base + OA + a_off + ko + i * 16 * PITCH);

            #pragma unroll
            for (int jb = 0; jb < 2; jb++) {
                uint32_t bh[4];
                ldm_x4(bh, base + OW + b_off + ko + jb * 16 * PITCH);
                #pragma unroll
                for (int h = 0; h < 2; h++) {
                    const int j = jb * 2 + h;
                    const uint32_t* ph = &bh[2 * h];
                    #pragma unroll
                    for (int i = 0; i < 2; i++)
                        mma16816_f16(acc[i][j], ah[i], ph);
                }
            }
        }
        __syncthreads();
    }

    // epilogue: store E = exp(2 * proj)
    #pragma unroll
    for (int i = 0; i < 2; i++) {
        const int r0 = wm * 32 + i * 16 + (lane >> 2);
        #pragma unroll
        for (int j = 0; j < 4; j++) {
            const int c0 = bn * 64 + wn * 32 + j * 8 + (lane & 3) * 2;
            *(float2*)(C + (size_t)r0 * 512 + c0) =
                make_float2(__expf(2.f * acc[i][j][0]), __expf(2.f * acc[i][j][1]));
            *(float2*)(C + (size_t)(r0 + 8) * 512 + c0) =
                make_float2(__expf(2.f * acc[i][j][2]), __expf(2.f * acc[i][j][3]));
        }
    }
}

// ---------------------------------------------------------------------------
// Score -> unnormalized p = exp(e) in g_a + per-quarter partial sums g_psum.
// e[t,s] = -2 * sum_k Va_k / (1 + Ea[t,k]*Eb[s,k])  (+const, cancels in
// softmax; |e| bounded ~36 -> exp safe in fp32, no max pass).
// Grid (TGT/TT, 4 s-quarters, BB) = 1024 blocks; tile 128 x 32, cp.async
// double-buffered; 4 blocks/SM.
// ---------------------------------------------------------------------------
#define STW (128 * 36)

__global__ void __launch_bounds__(256, 4) score_kernel(
    const float* __restrict__ Va,
    const int* __restrict__ mask)
{
    __shared__ float s_mp[2 * STW];     // 36 KB
    __shared__ float s_dp[TT * 512];    //  8 KB
    __shared__ float s_va[512];         //  2 KB
    __shared__ float s_red[TT * 4];

    const int b    = blockIdx.z;
    const int q4   = blockIdx.y;        // s-quarter 0..3
    const int t0   = blockIdx.x * TT;
    const int tid  = threadIdx.x;
    const int lane = tid & 31;
    const int w    = tid >> 5;
    const int wr4  = w & 3;             // row-group
    const int tg   = (w >> 2) * 2;      // t-pair base

    {
        const float4* dpg = (const float4*)(g_dp + (size_t)(b * TGT + t0) * 512);
        ((float4*)s_dp)[tid]       = dpg[tid];
        ((float4*)s_dp)[tid + 256] = dpg[tid + 256];
        if (tid < 128) ((float4*)s_va)[tid] = ((const float4*)Va)[tid];
    }

    const float* mpg = g_mp + (size_t)(b * SRC + q4 * 128) * 512;

    // loader: 1024 float4 per chunk, 4 per thread
    const int lr[4] = { (tid + 0) >> 3, (tid + 256) >> 3, (tid + 512) >> 3, (tid + 768) >> 3 };
    const int lc4   = (tid & 7) << 2;

    auto issue = [&](int kc, int buf) {
        float* dst = s_mp + buf * STW;
        const float* src = mpg + kc * 32;
        #pragma unroll
        for (int i = 0; i < 4; i++)
            cp_async16(dst + lr[i] * 36 + lc4, src + (size_t)lr[i] * 512 + lc4);
        CP_COMMIT();
    };

    issue(0, 0);

    float acc[2] = {0.f, 0.f};
    const int myrow = wr4 * 32 + lane;

    for (int c = 0; c < 16; c++) {
        if (c < 15) { issue(c + 1, (c + 1) & 1); CP_WAIT1(); }
        else        { CP_WAIT0(); }
        __syncthreads();

        const float* mrow_s = s_mp + (c & 1) * STW + myrow * 36;
        const int kc = c * 32;
        #pragma unroll
        for (int k = 0; k < 32; k += 4) {
            float4 m4 = *(const float4*)(mrow_s + k);           // Eb
            float4 v4 = *(const float4*)(s_va + kc + k);
            #pragma unroll
            for (int tt = 0; tt < 2; tt++) {
                float4 d4 = *(const float4*)(s_dp + (tg + tt) * 512 + kc + k);  // Ea
                float r0v = fast_rcp(fmaf(d4.x, m4.x, 1.f));
                float r1v = fast_rcp(fmaf(d4.y, m4.y, 1.f));
                float r2v = fast_rcp(fmaf(d4.z, m4.z, 1.f));
                float r3v = fast_rcp(fmaf(d4.w, m4.w, 1.f));
                acc[tt] = fmaf(v4.x, r0v, acc[tt]);
                acc[tt] = fmaf(v4.y, r1v, acc[tt]);
                acc[tt] = fmaf(v4.z, r2v, acc[tt]);
                acc[tt] = fmaf(v4.w, r3v, acc[tt]);
            }
        }
        __syncthreads();   // compute done before buffer refilled
    }

    // p = exp(-2*acc), masked to 0
    const int sg = q4 * 128 + myrow;
    const bool mok = (mask[b * SRC + sg] != 0);
    float p[2];
    #pragma unroll
    for (int tt = 0; tt < 2; tt++)
        p[tt] = mok ? __expf(-2.f * acc[tt]) : 0.f;

    // per-t partial sums over this block's 128 s (4 warps share each t)
    #pragma unroll
    for (int tt = 0; tt < 2; tt++) {
        float s = p[tt];
        #pragma unroll
        for (int o = 16; o; o >>= 1) s += __shfl_xor_sync(0xffffffffu, s, o);
        if (lane == 0) s_red[(tg + tt) * 4 + wr4] = s;
    }
    __syncthreads();
    if (tid < TT) {
        const float* r = s_red + tid * 4;
        g_psum[(b * TGT + t0 + tid) * 4 + q4] = r[0] + r[1] + r[2] + r[3];
    }

    #pragma unroll
    for (int tt = 0; tt < 2; tt++)
        g_a[(size_t)(b * TGT + t0 + tg + tt) * SRC + sg] = p[tt];
}

// ---------------------------------------------------------------------------
// Context GEMM + normalization:
// out[b,t,:] = (g_a[b,t,:] @ memory[b]) / sum_q psum[b,t,q]
// ---------------------------------------------------------------------------
__global__ void __launch_bounds__(256) context_kernel(
    const float* __restrict__ memory,
    float* __restrict__ out)
{
    __shared__ float As[64 * 32];
    __shared__ float Bs[32 * 32];

    const int cb  = blockIdx.x;
    const int tb  = blockIdx.y;
    const int b   = blockIdx.z;
    const int tid = threadIdx.x;
    const int col = tid & 31;
    const int tr0 = (tid >> 5) * 8;

    const float* Ab = g_a + (size_t)(b * TGT + tb * 64) * SRC;
    const float* Bb = memory + (size_t)b * SRC * ED + cb * 32;

    const int ar = tid >> 2;
    const int ac = (tid & 3) * 8;
    const int br = tid >> 3;
    const int bc = (tid & 7) * 4;

    float acc[8];
    #pragma unroll
    for (int i = 0; i < 8; i++) acc[i] = 0.f;

    for (int sc = 0; sc < SRC; sc += 32) {
        __syncthreads();
        *(float4*)(As + ar * 32 + ac)     = *(const float4*)(Ab + (size_t)ar * SRC + sc + ac);
        *(float4*)(As + ar * 32 + ac + 4) = *(const float4*)(Ab + (size_t)ar * SRC + sc + ac + 4);
        *(float4*)(Bs + br * 32 + bc)     = *(const float4*)(Bb + (size_t)(sc + br) * ED + bc);
        __syncthreads();

        #pragma unroll
        for (int s = 0; s < 32; s++) {
            float bv = Bs[s * 32 + col];
            #pragma unroll
            for (int i = 0; i < 8; i++)
                acc[i] = fmaf(As[(tr0 + i) * 32 + s], bv, acc[i]);
        }
    }

    #pragma unroll
    for (int i = 0; i < 8; i++) {
        const int t = tb * 64 + tr0 + i;
        const float* ps = g_psum + (b * TGT + t) * 4;
        const float inv = 1.f / (ps[0] + ps[1] + ps[2] + ps[3]);
        out[(size_t)(b * TGT + t) * ED + cb * 32 + col] = acc[i] * inv;
    }
}

// ---------------------------------------------------------------------------
extern "C" void kernel_launch(void* const* d_in, const int* in_sizes, int n_in,
                              void* d_out, int out_size)
{
    const float* memory = (const float*)d_in[0];
    const float* dec    = (const float*)d_in[1];
    const int*   mask   = (const int*)d_in[2];
    const float* Wa     = (const float*)d_in[3];
    const float* Va     = (const float*)d_in[4];
    float*       out    = (float*)d_out;

    (void)in_sizes; (void)n_in; (void)out_size;

    conv_a<<<2560, 256>>>(memory, dec);
    conv_w<<<dim3(16, 16, 2), dim3(32, 8)>>>(Wa);
    gemm_tc<<<dim3(8, 40), 256>>>();
    score_kernel<<<dim3(TGT / TT, 4, BB), 256>>>(Va, mask);
    context_kernel<<<dim3(16, 2, BB), 256>>>(memory, out);
}

// round 16
// speedup vs baseline: 1.3495x; 1.0478x over previous
#include <cuda_runtime.h>
#include <cuda_fp16.h>
#include <cstdint>

#define BB   8
#define SRC  512
#define TGT  128
#define ED   512
#define DD   512
#define TT   4

// Scratch (device globals: allocation-free per harness rules)
// NOTE: g_mp/g_dp hold Eb = exp(2*mp), Ea = exp(2*dp) (written by gemm_tc).
__device__ float g_mp[BB * SRC * DD];          // 8 MB
__device__ float g_dp[BB * TGT * DD];          // 2 MB
__device__ float g_a [BB * TGT * SRC];         // 2 MB: UNNORMALIZED exp(logit)
__device__ float g_psum[BB * TGT * 4];         // per-(b,t,s-quarter) partial sums
__device__ __half g_Ah[5120 * 512];            // A fp16 (memory rows 0..4095, dec 4096..5119)
__device__ __half g_Wt[2 * 512 * 512];         // W^T fp16: sel 0 = Wa_d, 1 = Wa_m; [n][k]

__device__ __forceinline__ float fast_rcp(float x) {
    float y;
    asm("rcp.approx.ftz.f32 %0, %1;" : "=f"(y) : "f"(x));   // bare MUFU.RCP
    return y;
}

__device__ __forceinline__ void cp_async16(void* smem_dst, const void* gmem_src) {
    uint32_t d = (uint32_t)__cvta_generic_to_shared(smem_dst);
    asm volatile("cp.async.ca.shared.global [%0], [%1], 16;\n" :: "r"(d), "l"(gmem_src));
}
#define CP_COMMIT() asm volatile("cp.async.commit_group;\n")
#define CP_WAIT1()  asm volatile("cp.async.wait_group 1;\n")
#define CP_WAIT0()  asm volatile("cp.async.wait_group 0;\n")

__device__ __forceinline__ void ldm_x4(uint32_t* r, uint32_t addr) {
    asm volatile("ldmatrix.sync.aligned.m8n8.x4.shared.b16 {%0,%1,%2,%3}, [%4];"
                 : "=r"(r[0]), "=r"(r[1]), "=r"(r[2]), "=r"(r[3]) : "r"(addr));
}
__device__ __forceinline__ void mma16816_f16(float* c, const uint32_t* a, const uint32_t* b) {
    asm volatile("mma.sync.aligned.m16n8k16.row.col.f32.f16.f16.f32 "
                 "{%0,%1,%2,%3}, {%4,%5,%6,%7}, {%8,%9}, {%0,%1,%2,%3};"
                 : "+f"(c[0]), "+f"(c[1]), "+f"(c[2]), "+f"(c[3])
                 : "r"(a[0]), "r"(a[1]), "r"(a[2]), "r"(a[3]), "r"(b[0]), "r"(b[1]));
}

// ---------------------------------------------------------------------------
// Fused conversion kernel.
// Blocks [0, 2560): A = [memory ; dec] fp32 -> fp16   (5120 x 512)
// Blocks [2560, 3072): W^T fp16: Wt[sel][n][k] = Wa[sel*512 + k][n]
// ---------------------------------------------------------------------------
__global__ void __launch_bounds__(256) conv_fused(
    const float* __restrict__ memory, const float* __restrict__ dec,
    const float* __restrict__ Wa)
{
    if (blockIdx.x < 2560) {
        const int idx = blockIdx.x * 256 + threadIdx.x;      // float4 index
        const float4 v = (idx < 524288) ? ((const float4*)memory)[idx]
                                        : ((const float4*)dec)[idx - 524288];
        ((__half2*)g_Ah)[idx * 2]     = __halves2half2(__float2half(v.x), __float2half(v.y));
        ((__half2*)g_Ah)[idx * 2 + 1] = __halves2half2(__float2half(v.z), __float2half(v.w));
    } else {
        __shared__ float s[32][33];
        const int bw  = blockIdx.x - 2560;                   // 0..511
        const int bx  = bw & 15, by = (bw >> 4) & 15, sel = bw >> 8;
        const int tx  = threadIdx.x & 31, ty = threadIdx.x >> 5;   // 32 x 8

        #pragma unroll
        for (int j = 0; j < 32; j += 8)
            s[ty + j][tx] = Wa[(size_t)(sel * 512 + by * 32 + ty + j) * 512 + bx * 32 + tx];
        __syncthreads();

        #pragma unroll
        for (int j = 0; j < 32; j += 8) {
            const int n = bx * 32 + ty + j;
            const int k = by * 32 + tx;
            g_Wt[(size_t)(sel * 512 + n) * 512 + k] = __float2half(s[tx][ty + j]);
        }
    }
}

// ---------------------------------------------------------------------------
// Tensor-core projection GEMM via mma.sync (single fp16, fp32 accum).
// C tile 128x64, grid (8,40)=320 CTAs, 3 CTAs/SM -> single wave.
// K-chunks of 64 -> 8 iterations (HALF the barrier pairs of R15).
// Dynamic smem 2 x 27648 = 55296 B (attribute set unconditionally on host).
// Pitch 144B = 9x16 -> ldmatrix phase banks (r+s) mod 8 distinct.
// Per k64-iter/warp: 16 ldmatrix.x4 + 32 mma.
// EPILOGUE stores exp(2*proj) for the score kernel's rcp formulation.
// ---------------------------------------------------------------------------
#define PITCH 144
#define OA    0
#define OW    (128 * PITCH)            // 18432
#define BUFSZ (192 * PITCH)            // 27648
#define GT_SMEM (2 * BUFSZ)            // 55296

__global__ void __launch_bounds__(256, 3) gemm_tc()
{
    extern __shared__ char sm[];
    const uint32_t sb = (uint32_t)__cvta_generic_to_shared(sm);

    const int tid  = threadIdx.x;
    const int lane = tid & 31;
    const int w    = tid >> 5;
    const int wm   = w >> 1;                      // 0..3 (m)
    const int wn   = w & 1;                       // 0..1 (n)
    const int bn   = blockIdx.x;                  // 0..7
    const int by   = blockIdx.y;                  // 0..39

    const int m_base = by * 128;
    const int sel    = (by < 32) ? 1 : 0;
    float* C = (by < 32) ? (g_mp + (size_t)by * 128 * 512)
                         : (g_dp + (size_t)(by - 32) * 128 * 512);
    const __half* Wp = g_Wt + (size_t)sel * 512 * 512 + (size_t)bn * 64 * 512;

    // loader: per chunk A 128 rows x 8 segs (1024) + W 64 x 8 (512) = 1536 cp16
    // thread covers 6: A ids tid, tid+256, tid+512, tid+768; W ids tid, tid+256
    auto issue = [&](int kc, int buf) {
        char* B = sm + buf * BUFSZ;
        const int kbase = kc * 64;
        #pragma unroll
        for (int i = 0; i < 4; i++) {
            const int id = i * 256 + tid;
            const int r = id >> 3, s = id & 7;
            cp_async16(B + OA + r * PITCH + s * 16,
                       g_Ah + (size_t)(m_base + r) * 512 + kbase + s * 8);
        }
        #pragma unroll
        for (int i = 0; i < 2; i++) {
            const int id = i * 256 + tid;
            const int r = id >> 3, s = id & 7;
            cp_async16(B + OW + r * PITCH + s * 16,
                       Wp + (size_t)r * 512 + kbase + s * 8);
        }
        CP_COMMIT();
    };

    // ldmatrix base offsets (+ kk*32 bytes selects k16 sub-chunk, kk = 0..3)
    const uint32_t a_off = (uint32_t)((wm * 32 + (lane & 15)) * PITCH + (lane >> 4) * 16);
    const uint32_t b_off = (uint32_t)((wn * 32 + (lane & 7) + ((lane >> 4) * 8)) * PITCH
                                      + (((lane >> 3) & 1) * 16));

    float acc[2][4][4];
    #pragma unroll
    for (int i = 0; i < 2; i++)
        #pragma unroll
        for (int j = 0; j < 4; j++)
            #pragma unroll
            for (int e = 0; e < 4; e++) acc[i][j][e] = 0.f;

    issue(0, 0);

    for (int kc = 0; kc < 8; kc++) {
        if (kc < 7) { issue(kc + 1, (kc + 1) & 1); CP_WAIT1(); }
        else        { CP_WAIT0(); }
        __syncthreads();

        const uint32_t base = sb + (kc & 1) * BUFSZ;
        #pragma unroll
        for (int kk = 0; kk < 4; kk++) {          // four k16 sub-chunks
            const uint32_t ko = kk * 32;
            uint32_t ah[2][4];
            #pragma unroll
            for (int i = 0; i < 2; i++)
                ldm_x4(ah[i], base + OA + a_off + ko + i * 16 * PITCH);

            #pragma unroll
            for (int jb = 0; jb < 2; jb++) {
                uint32_t bh[4];
                ldm_x4(bh, base + OW + b_off + ko + jb * 16 * PITCH);
                #pragma unroll
                for (int h = 0; h < 2; h++) {
                    const int j = jb * 2 + h;
                    const uint32_t* ph = &bh[2 * h];
                    #pragma unroll
                    for (int i = 0; i < 2; i++)
                        mma16816_f16(acc[i][j], ah[i], ph);
                }
            }
        }
        __syncthreads();
    }

    // epilogue: store E = exp(2 * proj)
    #pragma unroll
    for (int i = 0; i < 2; i++) {
        const int r0 = wm * 32 + i * 16 + (lane >> 2);
        #pragma unroll
        for (int j = 0; j < 4; j++) {
            const int c0 = bn * 64 + wn * 32 + j * 8 + (lane & 3) * 2;
            *(float2*)(C + (size_t)r0 * 512 + c0) =
                make_float2(__expf(2.f * acc[i][j][0]), __expf(2.f * acc[i][j][1]));
            *(float2*)(C + (size_t)(r0 + 8) * 512 + c0) =
                make_float2(__expf(2.f * acc[i][j][2]), __expf(2.f * acc[i][j][3]));
        }
    }
}

// ---------------------------------------------------------------------------
// Score -> unnormalized p = exp(e) in g_a + per-quarter partial sums g_psum.
// e[t,s] = -2 * sum_k Va_k / (1 + Ea[t,k]*Eb[s,k])  (+const, cancels in
// softmax; |e| bounded ~36 -> exp safe in fp32, no max pass).
// Grid (TGT/TT, 4 s-quarters, BB) = 1024 blocks; tile 128 x 32, cp.async
// double-buffered; 4 blocks/SM.  (Measured-best; at ~86% of MUFU-rcp floor.)
// ---------------------------------------------------------------------------
#define STW (128 * 36)

__global__ void __launch_bounds__(256, 4) score_kernel(
    const float* __restrict__ Va,
    const int* __restrict__ mask)
{
    __shared__ float s_mp[2 * STW];     // 36 KB
    __shared__ float s_dp[TT * 512];    //  8 KB
    __shared__ float s_va[512];         //  2 KB
    __shared__ float s_red[TT * 4];

    const int b    = blockIdx.z;
    const int q4   = blockIdx.y;        // s-quarter 0..3
    const int t0   = blockIdx.x * TT;
    const int tid  = threadIdx.x;
    const int lane = tid & 31;
    const int w    = tid >> 5;
    const int wr4  = w & 3;             // row-group
    const int tg   = (w >> 2) * 2;      // t-pair base

    {
        const float4* dpg = (const float4*)(g_dp + (size_t)(b * TGT + t0) * 512);
        ((float4*)s_dp)[tid]       = dpg[tid];
        ((float4*)s_dp)[tid + 256] = dpg[tid + 256];
        if (tid < 128) ((float4*)s_va)[tid] = ((const float4*)Va)[tid];
    }

    const float* mpg = g_mp + (size_t)(b * SRC + q4 * 128) * 512;

    // loader: 1024 float4 per chunk, 4 per thread
    const int lr[4] = { (tid + 0) >> 3, (tid + 256) >> 3, (tid + 512) >> 3, (tid + 768) >> 3 };
    const int lc4   = (tid & 7) << 2;

    auto issue = [&](int kc, int buf) {
        float* dst = s_mp + buf * STW;
        const float* src = mpg + kc * 32;
        #pragma unroll
        for (int i = 0; i < 4; i++)
            cp_async16(dst + lr[i] * 36 + lc4, src + (size_t)lr[i] * 512 + lc4);
        CP_COMMIT();
    };

    issue(0, 0);

    float acc[2] = {0.f, 0.f};
    const int myrow = wr4 * 32 + lane;

    for (int c = 0; c < 16; c++) {
        if (c < 15) { issue(c + 1, (c + 1) & 1); CP_WAIT1(); }
        else        { CP_WAIT0(); }
        __syncthreads();

        const float* mrow_s = s_mp + (c & 1) * STW + myrow * 36;
        const int kc = c * 32;
        #pragma unroll
        for (int k = 0; k < 32; k += 4) {
            float4 m4 = *(const float4*)(mrow_s + k);           // Eb
            float4 v4 = *(const float4*)(s_va + kc + k);
            #pragma unroll
            for (int tt = 0; tt < 2; tt++) {
                float4 d4 = *(const float4*)(s_dp + (tg + tt) * 512 + kc + k);  // Ea
                float r0v = fast_rcp(fmaf(d4.x, m4.x, 1.f));
                float r1v = fast_rcp(fmaf(d4.y, m4.y, 1.f));
                float r2v = fast_rcp(fmaf(d4.z, m4.z, 1.f));
                float r3v = fast_rcp(fmaf(d4.w, m4.w, 1.f));
                acc[tt] = fmaf(v4.x, r0v, acc[tt]);
                acc[tt] = fmaf(v4.y, r1v, acc[tt]);
                acc[tt] = fmaf(v4.z, r2v, acc[tt]);
                acc[tt] = fmaf(v4.w, r3v, acc[tt]);
            }
        }
        __syncthreads();   // compute done before buffer refilled
    }

    // p = exp(-2*acc), masked to 0
    const int sg = q4 * 128 + myrow;
    const bool mok = (mask[b * SRC + sg] != 0);
    float p[2];
    #pragma unroll
    for (int tt = 0; tt < 2; tt++)
        p[tt] = mok ? __expf(-2.f * acc[tt]) : 0.f;

    // per-t partial sums over this block's 128 s (4 warps share each t)
    #pragma unroll
    for (int tt = 0; tt < 2; tt++) {
        float s = p[tt];
        #pragma unroll
        for (int o = 16; o; o >>= 1) s += __shfl_xor_sync(0xffffffffu, s, o);
        if (lane == 0) s_red[(tg + tt) * 4 + wr4] = s;
    }
    __syncthreads();
    if (tid < TT) {
        const float* r = s_red + tid * 4;
        g_psum[(b * TGT + t0 + tid) * 4 + q4] = r[0] + r[1] + r[2] + r[3];
    }

    #pragma unroll
    for (int tt = 0; tt < 2; tt++)
        g_a[(size_t)(b * TGT + t0 + tg + tt) * SRC + sg] = p[tt];
}

// ---------------------------------------------------------------------------
// Context GEMM + normalization:
// out[b,t,:] = (g_a[b,t,:] @ memory[b]) / sum_q psum[b,t,q]
// ---------------------------------------------------------------------------
__global__ void __launch_bounds__(256) context_kernel(
    const float* __restrict__ memory,
    float* __restrict__ out)
{
    __shared__ float As[64 * 32];
    __shared__ float Bs[32 * 32];

    const int cb  = blockIdx.x;
    const int tb  = blockIdx.y;
    const int b   = blockIdx.z;
    const int tid = threadIdx.x;
    const int col = tid & 31;
    const int tr0 = (tid >> 5) * 8;

    const float* Ab = g_a + (size_t)(b * TGT + tb * 64) * SRC;
    const float* Bb = memory + (size_t)b * SRC * ED + cb * 32;

    const int ar = tid >> 2;
    const int ac = (tid & 3) * 8;
    const int br = tid >> 3;
    const int bc = (tid & 7) * 4;

    float acc[8];
    #pragma unroll
    for (int i = 0; i < 8; i++) acc[i] = 0.f;

    for (int sc = 0; sc < SRC; sc += 32) {
        __syncthreads();
        *(float4*)(As + ar * 32 + ac)     = *(const float4*)(Ab + (size_t)ar * SRC + sc + ac);
        *(float4*)(As + ar * 32 + ac + 4) = *(const float4*)(Ab + (size_t)ar * SRC + sc + ac + 4);
        *(float4*)(Bs + br * 32 + bc)     = *(const float4*)(Bb + (size_t)(sc + br) * ED + bc);
        __syncthreads();

        #pragma unroll
        for (int s = 0; s < 32; s++) {
            float bv = Bs[s * 32 + col];
            #pragma unroll
            for (int i = 0; i < 8; i++)
                acc[i] = fmaf(As[(tr0 + i) * 32 + s], bv, acc[i]);
        }
    }

    #pragma unroll
    for (int i = 0; i < 8; i++) {
        const int t = tb * 64 + tr0 + i;
        const float* ps = g_psum + (b * TGT + t) * 4;
        const float inv = 1.f / (ps[0] + ps[1] + ps[2] + ps[3]);
        out[(size_t)(b * TGT + t) * ED + cb * 32 + col] = acc[i] * inv;
    }
}

// ---------------------------------------------------------------------------
extern "C" void kernel_launch(void* const* d_in, const int* in_sizes, int n_in,
                              void* d_out, int out_size)
{
    const float* memory = (const float*)d_in[0];
    const float* dec    = (const float*)d_in[1];
    const int*   mask   = (const int*)d_in[2];
    const float* Wa     = (const float*)d_in[3];
    const float* Va     = (const float*)d_in[4];
    float*       out    = (float*)d_out;

    (void)in_sizes; (void)n_in; (void)out_size;

    // Unconditional (deterministic, capture-neutral, not an allocation).
    cudaFuncSetAttribute(gemm_tc, cudaFuncAttributeMaxDynamicSharedMemorySize, GT_SMEM);

    conv_fused<<<3072, 256>>>(memory, dec, Wa);
    gemm_tc<<<dim3(8, 40), 256, GT_SMEM>>>();
    score_kernel<<<dim3(TGT / TT, 4, BB), 256>>>(Va, mask);
    context_kernel<<<dim3(16, 2, BB), 256>>>(memory, out);
}